// round 1
// baseline (speedup 1.0000x reference)
#include <cuda_runtime.h>
#include <cstdint>

// Problem constants
#define IN_CH   128
#define OUT_CH  128
#define L_MAX   80          // L
#define NDEG    81          // L+1 degrees
#define NCPT    17
#define P_TOT   6561        // (L+1)^2
#define NBATCH  16
#define XB_STRIDE (IN_CH * P_TOT)   // 839808, batch stride in x/out

// Per-degree interpolated weights: wl_g[l][i][o], o contiguous. 5.25 MB.
__device__ float wl_g[NDEG * IN_CH * OUT_CH];

// ---------------------------------------------------------------------------
// Kernel 1: interpolate anchor weights -> per-degree matrices.
// weight layout: [in, out, ncpt] (trailing dim 1 dropped).
// Block = (i fixed, 32-wide o-chunk). Loads 32*17 anchors coalesced to smem,
// then writes 81*32 outputs with o-contiguous (coalesced) stores.
// ---------------------------------------------------------------------------
__global__ void shconv_interp(const float* __restrict__ w)
{
    __shared__ float anch[32][17];
    const int i  = blockIdx.x >> 2;
    const int o0 = (blockIdx.x & 3) * 32;
    const int base = (i * OUT_CH + o0) * NCPT;

    for (int e = threadIdx.x; e < 32 * NCPT; e += 256)
        anch[e / NCPT][e % NCPT] = w[base + e];
    __syncthreads();

    for (int e = threadIdx.x; e < NDEG * 32; e += 256) {
        const int l  = e >> 5;
        const int oo = e & 31;
        float v;
        if (l < 75) {                       // segments between anchors 0..15
            const int s = l / 5;
            const float t = (float)(l - s * 5) * 0.2f;
            v = (1.0f - t) * anch[oo][s] + t * anch[oo][s + 1];
        } else {                            // last segment: anchors 15..16, 6 pts
            const float t = (float)(l - 75) * 0.2f;
            v = (1.0f - t) * anch[oo][15] + t * anch[oo][16];
        }
        wl_g[(l * IN_CH + i) * OUT_CH + o0 + oo] = v;
    }
}

// ---------------------------------------------------------------------------
// Kernel 2: per-degree GEMM with packed f32x2 FMAs.
//   out[b,o,p] = sum_i wl_g[l(p)][i][o] * x[b,i,p]
// Tile: M=128 (all o) x N=64 (b,p)-columns of one degree x K=128 (all i).
// Grid: (41 max tiles, 81 degrees), early-exit on excess tiles.
// Threads: 256. tcq = tid&31 -> columns {tcq, tcq+32}; to2 = tid>>5 -> 16 o.
// x is staged into smem pre-duplicated as (v,v) u64 pairs so the inner loop
// is pure LDS + fma.rn.f32x2 (no per-FMA duplication movs).
// ---------------------------------------------------------------------------
__global__ __launch_bounds__(256) void shconv_gemm(const float* __restrict__ x,
                                                   float* __restrict__ out)
{
    const int l = blockIdx.y;
    const int ntiles = (l >> 1) + 1;                // ceil(16*(2l+1)/64)
    const int t = blockIdx.x;
    if (t >= ntiles) return;

    const int span  = 2 * l + 1;                    // positions for degree l
    const int ncols = 16 * span;                    // batch-expanded columns
    const int c0    = t * 64;

    __shared__ __align__(16) float              ws[16][128];  // 8 KB
    __shared__ __align__(16) unsigned long long xs2[16][64];  // 8 KB (x dup pairs)
    __shared__ int coloff[64];

    const int tid = threadIdx.x;

    if (tid < 64) {
        int c  = c0 + tid;
        int cc = c < ncols ? c : ncols - 1;         // clamp pads to a valid col
        int b  = cc / span;
        int pp = l * l + (cc - b * span);
        coloff[tid] = b * XB_STRIDE + pp;
    }
    __syncthreads();

    const int tcq = tid & 31;   // column lane (coalesced p across lanes)
    const int to2 = tid >> 5;   // o-group: o = to2*16 + [0..15]

    unsigned long long acc[2][8];
#pragma unroll
    for (int a = 0; a < 2; a++)
#pragma unroll
        for (int j = 0; j < 8; j++) acc[a][j] = 0ULL;

    const float* wbase = &wl_g[l * (IN_CH * OUT_CH)];

    for (int kk = 0; kk < IN_CH; kk += 16) {
        // stage ws[16][128]: 512 float4, 2 per thread, fully coalesced
#pragma unroll
        for (int j = 0; j < 2; j++) {
            int f  = tid + 256 * j;     // float4 index 0..511
            int k  = f >> 5;            // 32 float4 per 128-float row
            int oq = f & 31;
            *(float4*)&ws[k][oq * 4] =
                *(const float4*)&wbase[(kk + k) * OUT_CH + oq * 4];
        }
        // stage xs2[16][64] as duplicated pairs: 1024 elems, 4 per thread
#pragma unroll
        for (int j = 0; j < 4; j++) {
            int e = tid + 256 * j;
            int k = e >> 6;
            int c = e & 63;
            float v = x[coloff[c] + (kk + k) * P_TOT];
            unsigned int vi = __float_as_uint(v);
            xs2[k][c] = ((unsigned long long)vi << 32) | vi;
        }
        __syncthreads();

#pragma unroll
        for (int k = 0; k < 16; k++) {
            const unsigned long long xd0 = xs2[k][tcq];        // (x,x) col tcq
            const unsigned long long xd1 = xs2[k][tcq + 32];   // (x,x) col tcq+32
            const ulonglong2* wrow = (const ulonglong2*)&ws[k][to2 * 16];
            ulonglong2 w01 = wrow[0];   // pairs (o0,o1),(o2,o3)
            ulonglong2 w23 = wrow[1];
            ulonglong2 w45 = wrow[2];
            ulonglong2 w67 = wrow[3];
            unsigned long long wp[8] = { w01.x, w01.y, w23.x, w23.y,
                                         w45.x, w45.y, w67.x, w67.y };
#pragma unroll
            for (int j = 0; j < 8; j++) {
                asm("fma.rn.f32x2 %0, %1, %2, %0;"
                    : "+l"(acc[0][j]) : "l"(wp[j]), "l"(xd0));
                asm("fma.rn.f32x2 %0, %1, %2, %0;"
                    : "+l"(acc[1][j]) : "l"(wp[j]), "l"(xd1));
            }
        }
        __syncthreads();
    }

    // Store: lanes (tcq) sweep consecutive p -> coalesced 128B STG per instr.
#pragma unroll
    for (int a = 0; a < 2; a++) {
        const int c = c0 + tcq + 32 * a;
        if (c < ncols) {
            const int off = coloff[tcq + 32 * a];
#pragma unroll
            for (int j = 0; j < 8; j++) {
                const unsigned long long v = acc[a][j];
                const float lo = __uint_as_float((unsigned int)v);
                const float hi = __uint_as_float((unsigned int)(v >> 32));
                const int o = to2 * 16 + 2 * j;
                out[off + o * P_TOT]       = lo;
                out[off + (o + 1) * P_TOT] = hi;
            }
        }
    }
}

extern "C" void kernel_launch(void* const* d_in, const int* in_sizes, int n_in,
                              void* d_out, int out_size)
{
    const float* x = (const float*)d_in[0];      // [16,128,6561]
    const float* w = (const float*)d_in[1];      // [128,128,17,1]
    float* out = (float*)d_out;                  // [16,128,6561]

    shconv_interp<<<IN_CH * 4, 256>>>(w);        // 512 blocks

    dim3 grid(41, NDEG);                         // max tiles x degrees
    shconv_gemm<<<grid, 256>>>(x, out);
}